// round 1
// baseline (speedup 1.0000x reference)
#include <cuda_runtime.h>

// FasterPConv: B=2, N=80000, K=16, C=32, H=4, M=8
// out[b,n,m,c] = sum_k feat[b, inds[b,n,k], c] * guid[b,n,k,c/8] * wn[b,n,k,m]
//
// One warp per point (lane = channel c). 8 warps / 256-thread block.
// HBM-bound: ~275 MB total traffic -> ~45us floor.

#define B_ 2
#define N_ 80000
#define K_ 16
#define C_ 32
#define H_ 4
#define M_ 8

__global__ __launch_bounds__(256, 8)
void fasterpconv_kernel(const float* __restrict__ feat,
                        const int*   __restrict__ inds,
                        const float* __restrict__ guid,
                        const float* __restrict__ wn,
                        float*       __restrict__ out) {
    const int warp = threadIdx.x >> 5;
    const int lane = threadIdx.x & 31;
    const int point = blockIdx.x * 8 + warp;          // 0 .. 159999 (exact grid)

    __shared__ float s_g[8][K_ * H_];                 // 64 floats / point
    __shared__ float s_w[8][K_ * M_];                 // 128 floats / point
    __shared__ int   s_idx[8][K_];

    // Stage per-point data (coalesced GMEM loads, one warp per point).
    const float* gp = guid + (long)point * (K_ * H_);
    s_g[warp][lane]      = gp[lane];
    s_g[warp][lane + 32] = gp[lane + 32];

    const float* wp = wn + (long)point * (K_ * M_);
    #pragma unroll
    for (int i = 0; i < 4; i++)
        s_w[warp][lane + i * 32] = wp[lane + i * 32];

    if (lane < K_)
        s_idx[warp][lane] = inds[(long)point * K_ + lane];

    __syncwarp();

    // Gather all 16 neighbor features up front -> MLP=16 over the L2-resident table.
    const int b = point / N_;
    const float* fb = feat + (long)b * N_ * C_;
    float f[K_];
    #pragma unroll
    for (int k = 0; k < K_; k++)
        f[k] = fb[(long)s_idx[warp][k] * C_ + lane];

    const int head = lane >> 3;                       // C_/H_ = 8 channels per head
    float acc[M_];
    #pragma unroll
    for (int m = 0; m < M_; m++) acc[m] = 0.0f;

    #pragma unroll
    for (int k = 0; k < K_; k++) {
        const float gf = f[k] * s_g[warp][k * H_ + head];
        // 8 weights via two 128-bit broadcast LDS
        const float4 w0 = *reinterpret_cast<const float4*>(&s_w[warp][k * M_]);
        const float4 w1 = *reinterpret_cast<const float4*>(&s_w[warp][k * M_ + 4]);
        acc[0] += gf * w0.x;  acc[1] += gf * w0.y;
        acc[2] += gf * w0.z;  acc[3] += gf * w0.w;
        acc[4] += gf * w1.x;  acc[5] += gf * w1.y;
        acc[6] += gf * w1.z;  acc[7] += gf * w1.w;
    }

    // out[point, m*32 + lane] — each round is a coalesced 128B store per warp.
    float* op = out + (long)point * (M_ * C_);
    #pragma unroll
    for (int m = 0; m < M_; m++)
        op[m * C_ + lane] = acc[m];
}

extern "C" void kernel_launch(void* const* d_in, const int* in_sizes, int n_in,
                              void* d_out, int out_size) {
    const float* feat = (const float*)d_in[0];   // [B,N,C]
    const int*   inds = (const int*)  d_in[1];   // [B,N,K]
    const float* guid = (const float*)d_in[2];   // [B,N,K,H]
    const float* wn   = (const float*)d_in[3];   // [B,N,K,M]
    float* out = (float*)d_out;                  // [B,N,M*C]

    const int points = B_ * N_;                  // 160000, divisible by 8
    fasterpconv_kernel<<<points / 8, 256>>>(feat, inds, guid, wn, out);
}